// round 14
// baseline (speedup 1.0000x reference)
#include <cuda_runtime.h>
#include <cstdint>

#define BATCHN 8
#define SEQN   4096
#define NPOS   (BATCHN*SEQN)
#define VOCABN 257
#define QD     256
#define DEPTHN 6
#define BSV    (NPOS*VOCABN)

typedef unsigned long long ull;
typedef ulonglong2 ull2;

// ---------------- scratch (device globals; no allocations) ----------------
// g_wAll: 112 contiguous 64KB tiles: [0..96) = 6 layers x 16 tiles ([d][i][o] float4),
//         [96..112) = head retile [k4][j<256] float4
__device__ float4 g_wAll[112*4096];       // 7.34 MB
__device__ float  g_wH256[1024];          // w_head[256][k]
__device__ float  g_qA[VOCABN*QD*4];      // expand output q table (1.05 MB)
__device__ float  g_logits[VOCABN*VOCABN];// per-token logits (264 KB)
__device__ float  g_L[VOCABN];            // per-token mean |q_r|
__device__ float  g_part[NPOS/8];         // per-gather-block loss partials (4096)

// ---------------- packed f32x2 helpers ----------------
__device__ __forceinline__ ull bcast2(float x) {
    unsigned int u = __float_as_uint(x);
    ull r;
    asm("mov.b64 %0, {%1, %2};" : "=l"(r) : "r"(u), "r"(u));
    return r;
}
__device__ __forceinline__ ull pack2f(float a, float b) {
    ull r;
    asm("mov.b64 %0, {%1, %2};" : "=l"(r) : "r"(__float_as_uint(a)), "r"(__float_as_uint(b)));
    return r;
}
__device__ __forceinline__ void fma2(ull& d, ull a, ull b) {
    asm("fma.rn.f32x2 %0, %1, %2, %0;" : "+l"(d) : "l"(a), "l"(b));
}
__device__ __forceinline__ ull add2(ull a, ull b) {
    ull d;
    asm("add.rn.f32x2 %0, %1, %2;" : "=l"(d) : "l"(a), "l"(b));
    return d;
}
__device__ __forceinline__ float2 unpack2(ull v) {
    unsigned int lo, hi;
    asm("mov.b64 {%0, %1}, %2;" : "=r"(lo), "=r"(hi) : "l"(v));
    return make_float2(__uint_as_float(lo), __uint_as_float(hi));
}
#define NEG2 0x8000000080000000ULL

__device__ __forceinline__ uint32_t smem_u32(const void* p) {
    uint32_t a;
    asm("{ .reg .u64 t; cvta.to.shared.u64 t, %1; cvt.u32.u64 %0, t; }" : "=r"(a) : "l"(p));
    return a;
}
__device__ __forceinline__ uint32_t ctarank() {
    uint32_t r;
    asm("mov.u32 %0, %%cluster_ctarank;" : "=r"(r));
    return r;
}

#define MB_INIT(a, c) asm volatile("mbarrier.init.shared.b64 [%0], %1;" :: "r"(a), "r"(c) : "memory")
#define MB_EXPECT(a, b) asm volatile("mbarrier.arrive.expect_tx.shared.b64 _, [%0], %1;" :: "r"(a), "r"(b) : "memory")
#define MB_ARR_CL(addr, rk) \
    asm volatile("{\n\t.reg .b32 ra;\n\tmapa.shared::cluster.u32 ra, %0, %1;\n\t" \
                 "mbarrier.arrive.shared::cluster.b64 _, [ra];\n\t}" \
                 :: "r"(addr), "r"(rk) : "memory")
#define BULK_MC(dst, src, mbar) \
    asm volatile("cp.async.bulk.shared::cluster.global.mbarrier::complete_tx::bytes.multicast::cluster " \
                 "[%0], [%1], %2, [%3], %4;" \
                 :: "r"(dst), "l"(src), "r"(16384), "r"(mbar), "h"((unsigned short)0xF) : "memory")
#define MB_WAITP(mbar, ph) do { \
    asm volatile("{\n\t.reg .pred P1;\n\tWL_%=:\n\t" \
        "mbarrier.try_wait.parity.acquire.cta.shared::cta.b64 P1, [%0], %1, 0x989680;\n\t" \
        "@P1 bra.uni WD_%=;\n\tbra.uni WL_%=;\n\tWD_%=:\n\t}" \
        :: "r"(mbar), "r"(ph) : "memory"); \
} while (0)
#define CLUSTER_SYNC() do { \
    asm volatile("barrier.cluster.arrive.aligned;" ::: "memory"); \
    asm volatile("barrier.cluster.wait.aligned;" ::: "memory"); \
} while (0)

// ---------------- smem layout for k_mega (dynamic): 3-deep TMA ring ----------------
#define SM_WBUF   0          // 3 x 64KB weight tiles
#define SM_SQ     196608     // ull sq[256][4] = 8KB
#define SM_RED    204800     // ull red[3072] = 24KB
#define SM_SL     229376     // float sL[16]
#define SM_REDJ   229440     // float redj[2][32]
#define SM_MBAR   229696     // 6 mbarriers (3 full + 3 empty)
#define SM_TOTAL  229760

// ---------------- K0: all weight prep in one launch ----------------
__global__ void k_prep(const float* __restrict__ wl, const float* __restrict__ wh) {
    int b = blockIdx.x;
    int tid = threadIdx.x;
    __shared__ float4 tile[32][33];
    int col = tid & 31, row8 = tid >> 5;
    if (b < 384) {
        int d = b >> 6, r = b & 63;
        int it = r >> 3, ot = r & 7;
        const float* base = wl + (size_t)d * 4 * QD * QD;
#pragma unroll
        for (int s = 0; s < 4; s++) {
            int oo = row8 + s * 8;
            int o = ot * 32 + oo, i = it * 32 + col;
            float wr = base[0 * QD * QD + o * QD + i];
            float wi = base[1 * QD * QD + o * QD + i];
            float wj = base[2 * QD * QD + o * QD + i];
            float wk = base[3 * QD * QD + o * QD + i];
            tile[oo][col] = make_float4(wr, wi, wj, wk);
        }
        __syncthreads();
#pragma unroll
        for (int s = 0; s < 4; s++) {
            int ii = row8 + s * 8;
            int i = it * 32 + ii, o = ot * 32 + col;
            g_wAll[((size_t)d * QD + i) * QD + o] = tile[col][ii];
        }
    } else if (b < 448) {
        int b2 = b - 384;
        int jt = b2 >> 3, kt = b2 & 7;
#pragma unroll
        for (int s = 0; s < 4; s++) {
            int jj = row8 + s * 8;
            int j = jt * 32 + jj, k4 = kt * 32 + col;
            tile[jj][col] = *(const float4*)(wh + (size_t)j * 1024 + k4 * 4);
        }
        __syncthreads();
#pragma unroll
        for (int s = 0; s < 4; s++) {
            int kk = row8 + s * 8;
            int k4 = kt * 32 + kk, j = jt * 32 + col;
            g_wAll[96 * 4096 + (size_t)k4 * 256 + j] = tile[col][kk];
        }
    } else {
        for (int k = tid; k < 1024; k += 256) g_wH256[k] = wh[(size_t)256 * 1024 + k];
    }
}

// ---------------- K1: expansion stages, warp-per-output (coalesced W) ----------------
__global__ void k_expand(const float* __restrict__ emb,
                         const float* __restrict__ e0, const float* __restrict__ e1,
                         const float* __restrict__ e2, const float* __restrict__ e3,
                         const float* __restrict__ e4, const float* __restrict__ e5,
                         const float* __restrict__ e6, const float* __restrict__ e7) {
    __shared__ float4 bufA[QD];
    __shared__ float4 bufB[QD];
    int v = blockIdx.x, tid = threadIdx.x;
    int w = tid >> 5, lane = tid & 31;
    if (tid == 0)
        bufA[0] = make_float4(emb[v * 4 + 0], emb[v * 4 + 1], emb[v * 4 + 2], emb[v * 4 + 3]);
    __syncthreads();
    const float* ws[8] = {e0, e1, e2, e3, e4, e5, e6, e7};
    float4* cur = bufA;
    float4* nxt = bufB;
    for (int s = 0; s < 8; s++) {
        int cq = 1 << s, cq2 = cq * cq;
        const float* W = ws[s];
        for (int o = w; o < cq; o += 8) {
            float dr = 0.f, di = 0.f, dj = 0.f, dk = 0.f;
            for (int i = lane; i < cq; i += 32) {
                float4 q = cur[i];
                float wr = __ldg(W + o * cq + i);
                float wi = __ldg(W + cq2 + o * cq + i);
                float wj = __ldg(W + 2 * cq2 + o * cq + i);
                float wk = __ldg(W + 3 * cq2 + o * cq + i);
                dr += wr * q.x - wi * q.y - wj * q.z - wk * q.w;
                di += wi * q.x + wr * q.y + wk * q.z - wj * q.w;
                dj += wj * q.x - wk * q.y + wr * q.z + wi * q.w;
                dk += wk * q.x + wj * q.y - wi * q.z + wr * q.w;
            }
#pragma unroll
            for (int off = 16; off; off >>= 1) {
                dr += __shfl_down_sync(0xFFFFFFFFu, dr, off);
                di += __shfl_down_sync(0xFFFFFFFFu, di, off);
                dj += __shfl_down_sync(0xFFFFFFFFu, dj, off);
                dk += __shfl_down_sync(0xFFFFFFFFu, dk, off);
            }
            if (lane == 0) {
                dr = tanhf(dr); di = tanhf(di); dj = tanhf(dj); dk = tanhf(dk);
                float4 q = cur[o];
                nxt[o]      = make_float4(q.x + dr, q.y + di, q.z + dj, q.w + dk);
                nxt[o + cq] = make_float4(q.x - dr, q.y - di, q.z - dj, q.w - dk);
            }
        }
        __syncthreads();
        float4* t = cur; cur = nxt; nxt = t;
    }
    ((float4*)(g_qA + (size_t)v * 1024))[tid] = cur[tid];
}

// ---------------- MEGA: cluster-4, TMA-multicast, 3-deep ring, delayed refill ----------------
__global__ void __launch_bounds__(1024, 1) __cluster_dims__(4, 1, 1) k_mega() {
    extern __shared__ char sm[];
    uint32_t sb = smem_u32(sm);
    ull (*sq)[4]   = (ull(*)[4])(sm + SM_SQ);
    ull*  red      = (ull*)(sm + SM_RED);
    float* sL      = (float*)(sm + SM_SL);
    float (*redj)[32] = (float(*)[32])(sm + SM_REDJ);
    uint32_t mb = sb + SM_MBAR;   // full[i]=mb+8i, empty[i]=mb+24+8i

    int tid = threadIdx.x;
    int o = tid & 255, p = tid >> 8;
    uint32_t rank = ctarank();
    int b2 = blockIdx.x * 2;
    int t0 = b2 > 256 ? 256 : b2;
    int t1 = b2 + 1 > 256 ? 256 : b2 + 1;

    // load expand output into packed smem
    if (tid < 512) {
        int half = tid >> 8;
        int oo = tid & 255;
        int t = half ? t1 : t0;
        float4 a = ((const float4*)(g_qA + (size_t)t * 1024))[oo];
        ((float*)&sq[oo][0])[half] = a.x;
        ((float*)&sq[oo][1])[half] = a.y;
        ((float*)&sq[oo][2])[half] = a.z;
        ((float*)&sq[oo][3])[half] = a.w;
    }
    if (tid == 0) {
#pragma unroll
        for (int i = 0; i < 3; i++) {
            MB_INIT(mb + i * 8, 1);
            MB_INIT(mb + 24 + i * 8, 4);
        }
    }
    __syncthreads();
    CLUSTER_SYNC();   // all mbarriers visible cluster-wide before multicast

    const char* wall = (const char*)g_wAll;
    if (tid == 0) {
#pragma unroll
        for (int nt = 0; nt < 3; nt++) {
            MB_EXPECT(mb + nt * 8, 65536);
            BULK_MC(sb + SM_WBUF + nt * 65536 + rank * 16384,
                    wall + (size_t)nt * 65536 + rank * 16384, mb + nt * 8);
        }
    }
    int bufi = 0, ph = 0;          // ring position + parity (block-uniform)
    int g = 0;                     // global tile counter 0..111
    int ew0 = 0, ew1 = 0, ew2 = 0; // tid0-only per-buffer empty-wait parities

    // ---------------- 6 quaternion layers ----------------
    for (int d = 0; d < DEPTHN; d++) {
        ull P[16];
#pragma unroll
        for (int n = 0; n < 16; n++) P[n] = 0ull;

        for (int t = 0; t < 16; t++) {
            uint32_t fb = mb + bufi * 8, eb = mb + 24 + bufi * 8;
            MB_WAITP(fb, ph);
            const char* wtile = sm + SM_WBUF + bufi * 65536;
#pragma unroll
            for (int m = 0; m < 4; m++) {
                int il = p + 4 * m;
                float4 w = *(const float4*)(wtile + (((il << 8) + o) << 4));
                const ull* qp = &sq[t * 16 + il][0];
                ull wr = bcast2(w.x), wi = bcast2(w.y), wj = bcast2(w.z), wk = bcast2(w.w);
                ull2 qa = *(const ull2*)(qp);
                ull2 qc = *(const ull2*)(qp + 2);
                ull qr = qa.x, qi = qa.y, qj = qc.x, qk = qc.y;
                fma2(P[0],  wr, qr); fma2(P[1],  wr, qi); fma2(P[2],  wr, qj); fma2(P[3],  wr, qk);
                fma2(P[4],  wi, qr); fma2(P[5],  wi, qi); fma2(P[6],  wi, qj); fma2(P[7],  wi, qk);
                fma2(P[8],  wj, qr); fma2(P[9],  wj, qi); fma2(P[10], wj, qj); fma2(P[11], wj, qk);
                fma2(P[12], wk, qr); fma2(P[13], wk, qi); fma2(P[14], wk, qj); fma2(P[15], wk, qk);
            }
            __syncthreads();   // all threads done reading buffer bufi
            if (tid == 0) {
                MB_ARR_CL(eb, 0); MB_ARR_CL(eb, 1);
                MB_ARR_CL(eb, 2); MB_ARR_CL(eb, 3);
                // delayed refill: buffer consumed at tile g-1 gets tile g+2;
                // its empty arrivals completed a full tile ago -> fast-path wait
                if (g > 0 && g + 2 < 112) {
                    int tb = bufi == 0 ? 2 : bufi - 1;   // (g-1) % 3
                    int pw = tb == 0 ? ew0 : (tb == 1 ? ew1 : ew2);
                    MB_WAITP(mb + 24 + tb * 8, pw);
                    if (tb == 0) ew0 ^= 1; else if (tb == 1) ew1 ^= 1; else ew2 ^= 1;
                    uint32_t tfb = mb + tb * 8;
                    MB_EXPECT(tfb, 65536);
                    BULK_MC(sb + SM_WBUF + tb * 65536 + rank * 16384,
                            wall + (size_t)(g + 2) * 65536 + rank * 16384, tfb);
                }
            }
            g++;
            bufi++; if (bufi == 3) { bufi = 0; ph ^= 1; }
        }

        // Hamilton combine + normalize (packed over token pair)
        ull dr = add2(add2(P[0],  P[5]  ^ NEG2), add2(P[10] ^ NEG2, P[15] ^ NEG2));
        ull di = add2(add2(P[4],  P[1]),         add2(P[14],        P[11] ^ NEG2));
        ull dj = add2(add2(P[8],  P[13] ^ NEG2), add2(P[2],         P[7]));
        ull dk = add2(add2(P[12], P[9]),         add2(P[6]  ^ NEG2, P[3]));

        if (p) {
            int idx = ((p - 1) * 256 + o) * 4;
            red[idx] = dr; red[idx + 1] = di; red[idx + 2] = dj; red[idx + 3] = dk;
        }
        __syncthreads();
        if (p == 0) {
#pragma unroll
            for (int s = 0; s < 3; s++) {
                int idx = (s * 256 + o) * 4;
                dr = add2(dr, red[idx]);
                di = add2(di, red[idx + 1]);
                dj = add2(dj, red[idx + 2]);
                dk = add2(dk, red[idx + 3]);
            }
            float2 R = unpack2(dr), I = unpack2(di), J = unpack2(dj), K = unpack2(dk);
            float n0 = sqrtf(R.x * R.x + I.x * I.x + J.x * J.x + K.x * K.x);
            float v0 = 1.0f / (n0 + 1e-8f);
            float n1 = sqrtf(R.y * R.y + I.y * I.y + J.y * J.y + K.y * K.y);
            float v1 = 1.0f / (n1 + 1e-8f);
            sq[o][0] = pack2f(R.x * v0, R.y * v1);
            sq[o][1] = pack2f(I.x * v0, I.y * v1);
            sq[o][2] = pack2f(J.x * v0, J.y * v1);
            sq[o][3] = pack2f(K.x * v0, K.y * v1);
        }
        __syncthreads();
    }

    // ---------------- stability: mean |q_r| per token ----------------
    if (p == 0) {
        float2 qr = unpack2(sq[o][0]);
        float a0 = fabsf(qr.x), a1 = fabsf(qr.y);
#pragma unroll
        for (int off = 16; off; off >>= 1) {
            a0 += __shfl_down_sync(0xFFFFFFFFu, a0, off);
            a1 += __shfl_down_sync(0xFFFFFFFFu, a1, off);
        }
        if ((o & 31) == 0) {
            sL[(o >> 5) * 2 + 0] = a0;
            sL[(o >> 5) * 2 + 1] = a1;
        }
    }

    // build head hq: red[0..511] token0 (h[2m],h[2m+1]) pairs, red[512..1023] token1
    {
        int half = tid >> 9, idx = tid & 511;
        int oo = idx >> 1;
        int c0 = (2 * idx) & 3;
        float2 v0 = unpack2(sq[oo][c0]);
        float2 v1 = unpack2(sq[oo][c0 + 1]);
        red[half * 512 + idx] = half ? pack2f(v0.y, v1.y) : pack2f(v0.x, v1.x);
    }
    __syncthreads();

    if (tid == 0) {
        float s0 = 0.f, s1 = 0.f;
#pragma unroll
        for (int w = 0; w < 8; w++) { s0 += sL[w * 2]; s1 += sL[w * 2 + 1]; }
        g_L[t0] = s0 * (1.0f / QD);
        g_L[t1] = s1 * (1.0f / QD);
    }

    // j == 256 column (k = tid over 1024)
    {
        float w256 = g_wH256[tid];
        float s0 = w256 * ((const float*)red)[tid];
        float s1 = w256 * ((const float*)red)[1024 + tid];
#pragma unroll
        for (int off = 16; off; off >>= 1) {
            s0 += __shfl_down_sync(0xFFFFFFFFu, s0, off);
            s1 += __shfl_down_sync(0xFFFFFFFFu, s1, off);
        }
        if ((tid & 31) == 0) {
            redj[0][tid >> 5] = s0;
            redj[1][tid >> 5] = s1;
        }
    }

    // ---------------- head GEMM (tiles 96..111 of the same stream) ----------------
    {
        int j = o;
        ull a0 = 0ull, a1 = 0ull;
        for (int t = 0; t < 16; t++) {
            uint32_t fb = mb + bufi * 8, eb = mb + 24 + bufi * 8;
            MB_WAITP(fb, ph);
            const char* wtile = sm + SM_WBUF + bufi * 65536;
#pragma unroll
            for (int m = 0; m < 4; m++) {
                int il = p + 4 * m;
                int k4 = t * 16 + il;
                float4 w = *(const float4*)(wtile + (((il << 8) + j) << 4));
                ull w01 = *(const ull*)&w.x;
                ull w23 = *(const ull*)&w.z;
                ull2 qa = *(const ull2*)(red + 2 * k4);          // token0
                ull2 qb = *(const ull2*)(red + 512 + 2 * k4);    // token1
                fma2(a0, w01, qa.x); fma2(a0, w23, qa.y);
                fma2(a1, w01, qb.x); fma2(a1, w23, qb.y);
            }
            __syncthreads();
            if (tid == 0) {
                MB_ARR_CL(eb, 0); MB_ARR_CL(eb, 1);
                MB_ARR_CL(eb, 2); MB_ARR_CL(eb, 3);
                if (g + 2 < 112) {
                    int tb = bufi == 0 ? 2 : bufi - 1;
                    int pw = tb == 0 ? ew0 : (tb == 1 ? ew1 : ew2);
                    MB_WAITP(mb + 24 + tb * 8, pw);
                    if (tb == 0) ew0 ^= 1; else if (tb == 1) ew1 ^= 1; else ew2 ^= 1;
                    uint32_t tfb = mb + tb * 8;
                    MB_EXPECT(tfb, 65536);
                    BULK_MC(sb + SM_WBUF + tb * 65536 + rank * 16384,
                            wall + (size_t)(g + 2) * 65536 + rank * 16384, tfb);
                }
            }
            g++;
            bufi++; if (bufi == 3) { bufi = 0; ph ^= 1; }
        }

        ull* redh = red + 1024;   // token0: [0..767], token1: [768..1535]
        if (p) {
            redh[(p - 1) * 256 + j]       = a0;
            redh[768 + (p - 1) * 256 + j] = a1;
        }
        __syncthreads();
        if (p == 0) {
#pragma unroll
            for (int s = 0; s < 3; s++) {
                a0 = add2(a0, redh[s * 256 + j]);
                a1 = add2(a1, redh[768 + s * 256 + j]);
            }
            float2 r0 = unpack2(a0), r1 = unpack2(a1);
            g_logits[(size_t)t0 * VOCABN + j] = r0.x + r0.y;
            g_logits[(size_t)t1 * VOCABN + j] = r1.x + r1.y;
        }
        if (tid == 0) {
            float s0 = 0.f, s1 = 0.f;
#pragma unroll
            for (int w = 0; w < 32; w++) { s0 += redj[0][w]; s1 += redj[1][w]; }
            g_logits[(size_t)t0 * VOCABN + 256] = s0;
            g_logits[(size_t)t1 * VOCABN + 256] = s1;
        }
    }

    __syncthreads();
    CLUSTER_SYNC();   // no CTA exits while peer multicasts / remote arrives are in flight
}

// ---------------- K5: gather logits to output + loss partial (r10 proven) ----------------
__global__ void k_gather(const int* __restrict__ x, float* __restrict__ out) {
    __shared__ float ls[8];
    int warp = threadIdx.x >> 5, lane = threadIdx.x & 31;
    int pp = blockIdx.x * 8 + warp;
    int tok = x[pp];
    const float* row = g_logits + (size_t)tok * VOCABN;
    float* orow = out + (size_t)pp * VOCABN;
    for (int v = lane; v < VOCABN; v += 32)
        orow[v] = row[v];
    if (lane == 0) ls[warp] = g_L[tok];
    __syncthreads();
    if (threadIdx.x == 0) {
        float s = 0.f;
#pragma unroll
        for (int w = 0; w < 8; w++) s += ls[w];
        g_part[blockIdx.x] = s;
    }
}

// ---------------- K6: final loss reduction ----------------
__global__ void k_loss2(float* __restrict__ out, int out_size) {
    __shared__ float ws[32];
    int tid = threadIdx.x;
    float s = g_part[tid] + g_part[tid + 1024] + g_part[tid + 2048] + g_part[tid + 3072];
#pragma unroll
    for (int off = 16; off; off >>= 1)
        s += __shfl_down_sync(0xFFFFFFFFu, s, off);
    if ((tid & 31) == 0) ws[tid >> 5] = s;
    __syncthreads();
    if (tid < 32) {
        float v = ws[tid];
#pragma unroll
        for (int off = 16; off; off >>= 1)
            v += __shfl_down_sync(0xFFFFFFFFu, v, off);
        if (tid == 0 && out_size > BSV)
            out[BSV] = v * (1.0f / NPOS);
    }
}

// ---------------- launch ----------------
extern "C" void kernel_launch(void* const* d_in, const int* in_sizes, int n_in,
                              void* d_out, int out_size) {
    (void)in_sizes; (void)n_in;
    const int*   x   = (const int*)d_in[0];
    const float* emb = (const float*)d_in[1];
    const float* e0  = (const float*)d_in[2];
    const float* e1  = (const float*)d_in[3];
    const float* e2  = (const float*)d_in[4];
    const float* e3  = (const float*)d_in[5];
    const float* e4  = (const float*)d_in[6];
    const float* e5  = (const float*)d_in[7];
    const float* e6  = (const float*)d_in[8];
    const float* e7  = (const float*)d_in[9];
    const float* wl  = (const float*)d_in[10];
    const float* wh  = (const float*)d_in[11];
    float* out = (float*)d_out;

    static int smem_set = 0;
    if (!smem_set) {
        cudaFuncSetAttribute(k_mega, cudaFuncAttributeMaxDynamicSharedMemorySize, SM_TOTAL);
        smem_set = 1;
    }

    k_prep<<<449, 256>>>(wl, wh);
    k_expand<<<VOCABN, 256>>>(emb, e0, e1, e2, e3, e4, e5, e6, e7);
    k_mega<<<132, 1024, SM_TOTAL>>>();   // 33 clusters of 4
    k_gather<<<NPOS / 8, 256>>>(x, out);
    k_loss2<<<1, 1024>>>(out, out_size);
}

// round 15
// speedup vs baseline: 1.0027x; 1.0027x over previous
#include <cuda_runtime.h>
#include <cstdint>

#define BATCHN 8
#define SEQN   4096
#define NPOS   (BATCHN*SEQN)
#define VOCABN 257
#define QD     256
#define DEPTHN 6
#define BSV    (NPOS*VOCABN)

typedef unsigned long long ull;
typedef ulonglong2 ull2;

// ---------------- scratch (device globals; no allocations) ----------------
__device__ float4 g_wAll[112*4096];       // 7.34 MB: 96 layer tiles + 16 head tiles
__device__ float  g_wH256[1024];          // w_head[256][k]
__device__ float  g_qA[VOCABN*QD*4];      // expand output q table (1.05 MB)
__device__ float  g_logits[VOCABN*VOCABN];// per-token logits (264 KB)
__device__ float  g_L[VOCABN];            // per-token mean |q_r|
__device__ float  g_part[NPOS/8];         // per-gather-block loss partials (4096)
__device__ unsigned int g_cnt = 0;        // gather completion counter

// ---------------- packed f32x2 helpers ----------------
__device__ __forceinline__ ull bcast2(float x) {
    unsigned int u = __float_as_uint(x);
    ull r;
    asm("mov.b64 %0, {%1, %2};" : "=l"(r) : "r"(u), "r"(u));
    return r;
}
__device__ __forceinline__ ull pack2f(float a, float b) {
    ull r;
    asm("mov.b64 %0, {%1, %2};" : "=l"(r) : "r"(__float_as_uint(a)), "r"(__float_as_uint(b)));
    return r;
}
__device__ __forceinline__ void fma2(ull& d, ull a, ull b) {
    asm("fma.rn.f32x2 %0, %1, %2, %0;" : "+l"(d) : "l"(a), "l"(b));
}
__device__ __forceinline__ ull add2(ull a, ull b) {
    ull d;
    asm("add.rn.f32x2 %0, %1, %2;" : "=l"(d) : "l"(a), "l"(b));
    return d;
}
__device__ __forceinline__ float2 unpack2(ull v) {
    unsigned int lo, hi;
    asm("mov.b64 {%0, %1}, %2;" : "=r"(lo), "=r"(hi) : "l"(v));
    return make_float2(__uint_as_float(lo), __uint_as_float(hi));
}
#define NEG2 0x8000000080000000ULL

__device__ __forceinline__ uint32_t smem_u32(const void* p) {
    uint32_t a;
    asm("{ .reg .u64 t; cvta.to.shared.u64 t, %1; cvt.u32.u64 %0, t; }" : "=r"(a) : "l"(p));
    return a;
}
__device__ __forceinline__ uint32_t ctarank() {
    uint32_t r;
    asm("mov.u32 %0, %%cluster_ctarank;" : "=r"(r));
    return r;
}

#define MB_INIT(a, c) asm volatile("mbarrier.init.shared.b64 [%0], %1;" :: "r"(a), "r"(c) : "memory")
#define MB_EXPECT(a, b) asm volatile("mbarrier.arrive.expect_tx.shared.b64 _, [%0], %1;" :: "r"(a), "r"(b) : "memory")
#define MB_ARR_CL(addr, rk) \
    asm volatile("{\n\t.reg .b32 ra;\n\tmapa.shared::cluster.u32 ra, %0, %1;\n\t" \
                 "mbarrier.arrive.shared::cluster.b64 _, [ra];\n\t}" \
                 :: "r"(addr), "r"(rk) : "memory")
#define BULK_MC(dst, src, mbar) \
    asm volatile("cp.async.bulk.shared::cluster.global.mbarrier::complete_tx::bytes.multicast::cluster " \
                 "[%0], [%1], %2, [%3], %4;" \
                 :: "r"(dst), "l"(src), "r"(16384), "r"(mbar), "h"((unsigned short)0xF) : "memory")
#define MB_WAITP(mbar, ph) do { \
    asm volatile("{\n\t.reg .pred P1;\n\tWL_%=:\n\t" \
        "mbarrier.try_wait.parity.acquire.cta.shared::cta.b64 P1, [%0], %1, 0x989680;\n\t" \
        "@P1 bra.uni WD_%=;\n\tbra.uni WL_%=;\n\tWD_%=:\n\t}" \
        :: "r"(mbar), "r"(ph) : "memory"); \
} while (0)
#define CLUSTER_SYNC() do { \
    asm volatile("barrier.cluster.arrive.aligned;" ::: "memory"); \
    asm volatile("barrier.cluster.wait.aligned;" ::: "memory"); \
} while (0)

// ---------------- smem layout for k_mega (dynamic): 3-deep TMA ring ----------------
#define SM_WBUF   0          // 3 x 64KB weight tiles
#define SM_SQ     196608     // ull sq[256][4] = 8KB
#define SM_RED    204800     // ull red[3072] = 24KB
#define SM_SL     229376     // float sL[16]
#define SM_REDJ   229440     // float redj[2][32]
#define SM_MBAR   229696     // 6 mbarriers (3 full + 3 empty)
#define SM_TOTAL  229760

// ---------------- K0: all weight prep in one launch ----------------
__global__ void k_prep(const float* __restrict__ wl, const float* __restrict__ wh) {
    int b = blockIdx.x;
    int tid = threadIdx.x;
    __shared__ float4 tile[32][33];
    int col = tid & 31, row8 = tid >> 5;
    if (b < 384) {
        int d = b >> 6, r = b & 63;
        int it = r >> 3, ot = r & 7;
        const float* base = wl + (size_t)d * 4 * QD * QD;
#pragma unroll
        for (int s = 0; s < 4; s++) {
            int oo = row8 + s * 8;
            int o = ot * 32 + oo, i = it * 32 + col;
            float wr = base[0 * QD * QD + o * QD + i];
            float wi = base[1 * QD * QD + o * QD + i];
            float wj = base[2 * QD * QD + o * QD + i];
            float wk = base[3 * QD * QD + o * QD + i];
            tile[oo][col] = make_float4(wr, wi, wj, wk);
        }
        __syncthreads();
#pragma unroll
        for (int s = 0; s < 4; s++) {
            int ii = row8 + s * 8;
            int i = it * 32 + ii, o = ot * 32 + col;
            g_wAll[((size_t)d * QD + i) * QD + o] = tile[col][ii];
        }
    } else if (b < 448) {
        int b2 = b - 384;
        int jt = b2 >> 3, kt = b2 & 7;
#pragma unroll
        for (int s = 0; s < 4; s++) {
            int jj = row8 + s * 8;
            int j = jt * 32 + jj, k4 = kt * 32 + col;
            tile[jj][col] = *(const float4*)(wh + (size_t)j * 1024 + k4 * 4);
        }
        __syncthreads();
#pragma unroll
        for (int s = 0; s < 4; s++) {
            int kk = row8 + s * 8;
            int k4 = kt * 32 + kk, j = jt * 32 + col;
            g_wAll[96 * 4096 + (size_t)k4 * 256 + j] = tile[col][kk];
        }
    } else {
        for (int k = tid; k < 1024; k += 256) g_wH256[k] = wh[(size_t)256 * 1024 + k];
    }
}

// ---------------- K1: expansion stages, warp-per-output (coalesced W) ----------------
__global__ void k_expand(const float* __restrict__ emb,
                         const float* __restrict__ e0, const float* __restrict__ e1,
                         const float* __restrict__ e2, const float* __restrict__ e3,
                         const float* __restrict__ e4, const float* __restrict__ e5,
                         const float* __restrict__ e6, const float* __restrict__ e7) {
    __shared__ float4 bufA[QD];
    __shared__ float4 bufB[QD];
    int v = blockIdx.x, tid = threadIdx.x;
    int w = tid >> 5, lane = tid & 31;
    if (tid == 0)
        bufA[0] = make_float4(emb[v * 4 + 0], emb[v * 4 + 1], emb[v * 4 + 2], emb[v * 4 + 3]);
    __syncthreads();
    const float* ws[8] = {e0, e1, e2, e3, e4, e5, e6, e7};
    float4* cur = bufA;
    float4* nxt = bufB;
    for (int s = 0; s < 8; s++) {
        int cq = 1 << s, cq2 = cq * cq;
        const float* W = ws[s];
        for (int o = w; o < cq; o += 8) {
            float dr = 0.f, di = 0.f, dj = 0.f, dk = 0.f;
            for (int i = lane; i < cq; i += 32) {
                float4 q = cur[i];
                float wr = __ldg(W + o * cq + i);
                float wi = __ldg(W + cq2 + o * cq + i);
                float wj = __ldg(W + 2 * cq2 + o * cq + i);
                float wk = __ldg(W + 3 * cq2 + o * cq + i);
                dr += wr * q.x - wi * q.y - wj * q.z - wk * q.w;
                di += wi * q.x + wr * q.y + wk * q.z - wj * q.w;
                dj += wj * q.x - wk * q.y + wr * q.z + wi * q.w;
                dk += wk * q.x + wj * q.y - wi * q.z + wr * q.w;
            }
#pragma unroll
            for (int off = 16; off; off >>= 1) {
                dr += __shfl_down_sync(0xFFFFFFFFu, dr, off);
                di += __shfl_down_sync(0xFFFFFFFFu, di, off);
                dj += __shfl_down_sync(0xFFFFFFFFu, dj, off);
                dk += __shfl_down_sync(0xFFFFFFFFu, dk, off);
            }
            if (lane == 0) {
                dr = tanhf(dr); di = tanhf(di); dj = tanhf(dj); dk = tanhf(dk);
                float4 q = cur[o];
                nxt[o]      = make_float4(q.x + dr, q.y + di, q.z + dj, q.w + dk);
                nxt[o + cq] = make_float4(q.x - dr, q.y - di, q.z - dj, q.w - dk);
            }
        }
        __syncthreads();
        float4* t = cur; cur = nxt; nxt = t;
    }
    ((float4*)(g_qA + (size_t)v * 1024))[tid] = cur[tid];
}

// ---------------- MEGA: cluster-4, TMA-multicast, 3-deep ring (r10 proven) ----------------
__global__ void __launch_bounds__(1024, 1) __cluster_dims__(4, 1, 1) k_mega() {
    extern __shared__ char sm[];
    uint32_t sb = smem_u32(sm);
    ull (*sq)[4]   = (ull(*)[4])(sm + SM_SQ);
    ull*  red      = (ull*)(sm + SM_RED);
    float* sL      = (float*)(sm + SM_SL);
    float (*redj)[32] = (float(*)[32])(sm + SM_REDJ);
    uint32_t mb = sb + SM_MBAR;   // full[i]=mb+8i, empty[i]=mb+24+8i

    int tid = threadIdx.x;
    int o = tid & 255, p = tid >> 8;
    uint32_t rank = ctarank();
    int b2 = blockIdx.x * 2;
    int t0 = b2 > 256 ? 256 : b2;
    int t1 = b2 + 1 > 256 ? 256 : b2 + 1;

    // load expand output into packed smem
    if (tid < 512) {
        int half = tid >> 8;
        int oo = tid & 255;
        int t = half ? t1 : t0;
        float4 a = ((const float4*)(g_qA + (size_t)t * 1024))[oo];
        ((float*)&sq[oo][0])[half] = a.x;
        ((float*)&sq[oo][1])[half] = a.y;
        ((float*)&sq[oo][2])[half] = a.z;
        ((float*)&sq[oo][3])[half] = a.w;
    }
    if (tid == 0) {
#pragma unroll
        for (int i = 0; i < 3; i++) {
            MB_INIT(mb + i * 8, 1);
            MB_INIT(mb + 24 + i * 8, 4);
        }
    }
    __syncthreads();
    CLUSTER_SYNC();   // all mbarriers visible cluster-wide before multicast

    const char* wall = (const char*)g_wAll;
    if (tid == 0) {
#pragma unroll
        for (int nt = 0; nt < 3; nt++) {
            MB_EXPECT(mb + nt * 8, 65536);
            BULK_MC(sb + SM_WBUF + nt * 65536 + rank * 16384,
                    wall + (size_t)nt * 65536 + rank * 16384, mb + nt * 8);
        }
    }
    int bufi = 0, ph = 0;   // ring position + parity (all threads track identically)

    // ---------------- 6 quaternion layers ----------------
    for (int d = 0; d < DEPTHN; d++) {
        ull P[16];
#pragma unroll
        for (int n = 0; n < 16; n++) P[n] = 0ull;

        for (int t = 0; t < 16; t++) {
            uint32_t fb = mb + bufi * 8, eb = mb + 24 + bufi * 8;
            MB_WAITP(fb, ph);
            const char* wtile = sm + SM_WBUF + bufi * 65536;
#pragma unroll
            for (int m = 0; m < 4; m++) {
                int il = p + 4 * m;
                float4 w = *(const float4*)(wtile + (((il << 8) + o) << 4));
                const ull* qp = &sq[t * 16 + il][0];
                ull wr = bcast2(w.x), wi = bcast2(w.y), wj = bcast2(w.z), wk = bcast2(w.w);
                ull2 qa = *(const ull2*)(qp);
                ull2 qc = *(const ull2*)(qp + 2);
                ull qr = qa.x, qi = qa.y, qj = qc.x, qk = qc.y;
                fma2(P[0],  wr, qr); fma2(P[1],  wr, qi); fma2(P[2],  wr, qj); fma2(P[3],  wr, qk);
                fma2(P[4],  wi, qr); fma2(P[5],  wi, qi); fma2(P[6],  wi, qj); fma2(P[7],  wi, qk);
                fma2(P[8],  wj, qr); fma2(P[9],  wj, qi); fma2(P[10], wj, qj); fma2(P[11], wj, qk);
                fma2(P[12], wk, qr); fma2(P[13], wk, qi); fma2(P[14], wk, qj); fma2(P[15], wk, qk);
            }
            __syncthreads();   // all threads done reading buffer bufi
            if (tid == 0) {
                MB_ARR_CL(eb, 0); MB_ARR_CL(eb, 1);
                MB_ARR_CL(eb, 2); MB_ARR_CL(eb, 3);
                int nt2 = d * 16 + t + 3;
                if (nt2 < 112) {
                    MB_WAITP(eb, ph);
                    MB_EXPECT(fb, 65536);
                    BULK_MC(sb + SM_WBUF + bufi * 65536 + rank * 16384,
                            wall + (size_t)nt2 * 65536 + rank * 16384, fb);
                }
            }
            bufi++; if (bufi == 3) { bufi = 0; ph ^= 1; }
        }

        // Hamilton combine + normalize (packed over token pair)
        ull dr = add2(add2(P[0],  P[5]  ^ NEG2), add2(P[10] ^ NEG2, P[15] ^ NEG2));
        ull di = add2(add2(P[4],  P[1]),         add2(P[14],        P[11] ^ NEG2));
        ull dj = add2(add2(P[8],  P[13] ^ NEG2), add2(P[2],         P[7]));
        ull dk = add2(add2(P[12], P[9]),         add2(P[6]  ^ NEG2, P[3]));

        if (p) {
            int idx = ((p - 1) * 256 + o) * 4;
            red[idx] = dr; red[idx + 1] = di; red[idx + 2] = dj; red[idx + 3] = dk;
        }
        __syncthreads();
        if (p == 0) {
#pragma unroll
            for (int s = 0; s < 3; s++) {
                int idx = (s * 256 + o) * 4;
                dr = add2(dr, red[idx]);
                di = add2(di, red[idx + 1]);
                dj = add2(dj, red[idx + 2]);
                dk = add2(dk, red[idx + 3]);
            }
            float2 R = unpack2(dr), I = unpack2(di), J = unpack2(dj), K = unpack2(dk);
            float n0 = sqrtf(R.x * R.x + I.x * I.x + J.x * J.x + K.x * K.x);
            float v0 = 1.0f / (n0 + 1e-8f);
            float n1 = sqrtf(R.y * R.y + I.y * I.y + J.y * J.y + K.y * K.y);
            float v1 = 1.0f / (n1 + 1e-8f);
            sq[o][0] = pack2f(R.x * v0, R.y * v1);
            sq[o][1] = pack2f(I.x * v0, I.y * v1);
            sq[o][2] = pack2f(J.x * v0, J.y * v1);
            sq[o][3] = pack2f(K.x * v0, K.y * v1);
        }
        __syncthreads();
    }

    // ---------------- stability: mean |q_r| per token ----------------
    if (p == 0) {
        float2 qr = unpack2(sq[o][0]);
        float a0 = fabsf(qr.x), a1 = fabsf(qr.y);
#pragma unroll
        for (int off = 16; off; off >>= 1) {
            a0 += __shfl_down_sync(0xFFFFFFFFu, a0, off);
            a1 += __shfl_down_sync(0xFFFFFFFFu, a1, off);
        }
        if ((o & 31) == 0) {
            sL[(o >> 5) * 2 + 0] = a0;
            sL[(o >> 5) * 2 + 1] = a1;
        }
    }

    // build head hq: red[0..511] token0 (h[2m],h[2m+1]) pairs, red[512..1023] token1
    {
        int half = tid >> 9, idx = tid & 511;
        int oo = idx >> 1;
        int c0 = (2 * idx) & 3;
        float2 v0 = unpack2(sq[oo][c0]);
        float2 v1 = unpack2(sq[oo][c0 + 1]);
        red[half * 512 + idx] = half ? pack2f(v0.y, v1.y) : pack2f(v0.x, v1.x);
    }
    __syncthreads();

    if (tid == 0) {
        float s0 = 0.f, s1 = 0.f;
#pragma unroll
        for (int w = 0; w < 8; w++) { s0 += sL[w * 2]; s1 += sL[w * 2 + 1]; }
        g_L[t0] = s0 * (1.0f / QD);
        g_L[t1] = s1 * (1.0f / QD);
    }

    // j == 256 column (k = tid over 1024)
    {
        float w256 = g_wH256[tid];
        float s0 = w256 * ((const float*)red)[tid];
        float s1 = w256 * ((const float*)red)[1024 + tid];
#pragma unroll
        for (int off = 16; off; off >>= 1) {
            s0 += __shfl_down_sync(0xFFFFFFFFu, s0, off);
            s1 += __shfl_down_sync(0xFFFFFFFFu, s1, off);
        }
        if ((tid & 31) == 0) {
            redj[0][tid >> 5] = s0;
            redj[1][tid >> 5] = s1;
        }
    }

    // ---------------- head GEMM (tiles 96..111 of the same stream) ----------------
    {
        int j = o;
        ull a0 = 0ull, a1 = 0ull;
        for (int t = 0; t < 16; t++) {
            uint32_t fb = mb + bufi * 8, eb = mb + 24 + bufi * 8;
            MB_WAITP(fb, ph);
            const char* wtile = sm + SM_WBUF + bufi * 65536;
#pragma unroll
            for (int m = 0; m < 4; m++) {
                int il = p + 4 * m;
                int k4 = t * 16 + il;
                float4 w = *(const float4*)(wtile + (((il << 8) + j) << 4));
                ull w01 = *(const ull*)&w.x;
                ull w23 = *(const ull*)&w.z;
                ull2 qa = *(const ull2*)(red + 2 * k4);          // token0
                ull2 qb = *(const ull2*)(red + 512 + 2 * k4);    // token1
                fma2(a0, w01, qa.x); fma2(a0, w23, qa.y);
                fma2(a1, w01, qb.x); fma2(a1, w23, qb.y);
            }
            __syncthreads();
            if (tid == 0) {
                MB_ARR_CL(eb, 0); MB_ARR_CL(eb, 1);
                MB_ARR_CL(eb, 2); MB_ARR_CL(eb, 3);
                int nt2 = 96 + t + 3;
                if (nt2 < 112) {
                    MB_WAITP(eb, ph);
                    MB_EXPECT(fb, 65536);
                    BULK_MC(sb + SM_WBUF + bufi * 65536 + rank * 16384,
                            wall + (size_t)nt2 * 65536 + rank * 16384, fb);
                }
            }
            bufi++; if (bufi == 3) { bufi = 0; ph ^= 1; }
        }

        ull* redh = red + 1024;   // token0: [0..767], token1: [768..1535]
        if (p) {
            redh[(p - 1) * 256 + j]       = a0;
            redh[768 + (p - 1) * 256 + j] = a1;
        }
        __syncthreads();
        if (p == 0) {
#pragma unroll
            for (int s = 0; s < 3; s++) {
                a0 = add2(a0, redh[s * 256 + j]);
                a1 = add2(a1, redh[768 + s * 256 + j]);
            }
            float2 r0 = unpack2(a0), r1 = unpack2(a1);
            g_logits[(size_t)t0 * VOCABN + j] = r0.x + r0.y;
            g_logits[(size_t)t1 * VOCABN + j] = r1.x + r1.y;
        }
        if (tid == 0) {
            float s0 = 0.f, s1 = 0.f;
#pragma unroll
            for (int w = 0; w < 32; w++) { s0 += redj[0][w]; s1 += redj[1][w]; }
            g_logits[(size_t)t0 * VOCABN + 256] = s0;
            g_logits[(size_t)t1 * VOCABN + 256] = s1;
        }
    }

    __syncthreads();
    CLUSTER_SYNC();   // no CTA exits while peer multicasts / remote arrives are in flight
}

// ---------------- K5: gather, block-linear coalesced + fused final loss ----------------
// block = 8 output rows = 2056 contiguous floats; 256 threads write linearly.
__global__ void k_gather(const int* __restrict__ x, float* __restrict__ out, int out_size) {
    __shared__ int   stok[8];
    __shared__ float ls[8];
    __shared__ float redf[256];
    __shared__ int   is_last;
    int tid = threadIdx.x;
    int bid = blockIdx.x;
    if (tid < 8) {
        int tok = x[bid * 8 + tid];
        stok[tid] = tok;
        ls[tid] = g_L[tok];
    }
    __syncthreads();

    float* obase = out + (size_t)bid * (8 * VOCABN);
#pragma unroll
    for (int k = 0; k < 9; k++) {
        int idx = tid + k * 256;
        if (idx < 8 * VOCABN) {
            unsigned r = (unsigned)idx / 257u;
            unsigned v = (unsigned)idx - r * 257u;
            obase[idx] = g_logits[(size_t)stok[r] * VOCABN + v];
        }
    }

    // loss partial + completion counter
    if (tid == 0) {
        float s = 0.f;
#pragma unroll
        for (int w = 0; w < 8; w++) s += ls[w];
        g_part[bid] = s;
        __threadfence();
        unsigned old = atomicAdd(&g_cnt, 1u);
        is_last = (old == (unsigned)(NPOS / 8 - 1));
    }
    __syncthreads();

    if (is_last) {
        __threadfence();
        float s = 0.f;
        for (int i = tid; i < NPOS / 8; i += 256)
            s += g_part[i];
        redf[tid] = s;
        __syncthreads();
        for (int k2 = 128; k2 > 0; k2 >>= 1) {
            if (tid < k2) redf[tid] += redf[tid + k2];
            __syncthreads();
        }
        if (tid == 0) {
            if (out_size > BSV) out[BSV] = redf[0] * (1.0f / NPOS);
            g_cnt = 0;   // reset for the next (deterministic) replay
        }
    }
}

// ---------------- launch ----------------
extern "C" void kernel_launch(void* const* d_in, const int* in_sizes, int n_in,
                              void* d_out, int out_size) {
    (void)in_sizes; (void)n_in;
    const int*   x   = (const int*)d_in[0];
    const float* emb = (const float*)d_in[1];
    const float* e0  = (const float*)d_in[2];
    const float* e1  = (const float*)d_in[3];
    const float* e2  = (const float*)d_in[4];
    const float* e3  = (const float*)d_in[5];
    const float* e4  = (const float*)d_in[6];
    const float* e5  = (const float*)d_in[7];
    const float* e6  = (const float*)d_in[8];
    const float* e7  = (const float*)d_in[9];
    const float* wl  = (const float*)d_in[10];
    const float* wh  = (const float*)d_in[11];
    float* out = (float*)d_out;

    static int smem_set = 0;
    if (!smem_set) {
        cudaFuncSetAttribute(k_mega, cudaFuncAttributeMaxDynamicSharedMemorySize, SM_TOTAL);
        smem_set = 1;
    }

    k_prep<<<449, 256>>>(wl, wh);
    k_expand<<<VOCABN, 256>>>(emb, e0, e1, e2, e3, e4, e5, e6, e7);
    k_mega<<<132, 1024, SM_TOTAL>>>();   // 33 clusters of 4
    k_gather<<<NPOS / 8, 256>>>(x, out, out_size);
}

// round 16
// speedup vs baseline: 1.0364x; 1.0337x over previous
#include <cuda_runtime.h>
#include <cstdint>

#define BATCHN 8
#define SEQN   4096
#define NPOS   (BATCHN*SEQN)
#define VOCABN 257
#define QD     256
#define DEPTHN 6
#define BSV    (NPOS*VOCABN)

typedef unsigned long long ull;
typedef ulonglong2 ull2;

// ---------------- scratch (device globals; no allocations) ----------------
__device__ float4 g_wAll[112*4096];       // 7.34 MB: 96 layer tiles + 16 head tiles
__device__ float  g_wH256[1024];          // w_head[256][k]
__device__ float  g_logits[VOCABN*VOCABN];// per-token logits (264 KB)
__device__ float  g_L[VOCABN];            // per-token mean |q_r|
__device__ float  g_part[NPOS/8];         // per-gather-block loss partials (4096)
__device__ unsigned int g_cnt = 0;        // gather completion counter

// ---------------- packed f32x2 helpers ----------------
__device__ __forceinline__ ull bcast2(float x) {
    unsigned int u = __float_as_uint(x);
    ull r;
    asm("mov.b64 %0, {%1, %2};" : "=l"(r) : "r"(u), "r"(u));
    return r;
}
__device__ __forceinline__ ull pack2f(float a, float b) {
    ull r;
    asm("mov.b64 %0, {%1, %2};" : "=l"(r) : "r"(__float_as_uint(a)), "r"(__float_as_uint(b)));
    return r;
}
__device__ __forceinline__ void fma2(ull& d, ull a, ull b) {
    asm("fma.rn.f32x2 %0, %1, %2, %0;" : "+l"(d) : "l"(a), "l"(b));
}
__device__ __forceinline__ ull add2(ull a, ull b) {
    ull d;
    asm("add.rn.f32x2 %0, %1, %2;" : "=l"(d) : "l"(a), "l"(b));
    return d;
}
__device__ __forceinline__ float2 unpack2(ull v) {
    unsigned int lo, hi;
    asm("mov.b64 {%0, %1}, %2;" : "=r"(lo), "=r"(hi) : "l"(v));
    return make_float2(__uint_as_float(lo), __uint_as_float(hi));
}
#define NEG2 0x8000000080000000ULL

__device__ __forceinline__ uint32_t smem_u32(const void* p) {
    uint32_t a;
    asm("{ .reg .u64 t; cvta.to.shared.u64 t, %1; cvt.u32.u64 %0, t; }" : "=r"(a) : "l"(p));
    return a;
}
__device__ __forceinline__ uint32_t ctarank() {
    uint32_t r;
    asm("mov.u32 %0, %%cluster_ctarank;" : "=r"(r));
    return r;
}

#define MB_INIT(a, c) asm volatile("mbarrier.init.shared.b64 [%0], %1;" :: "r"(a), "r"(c) : "memory")
#define MB_EXPECT(a, b) asm volatile("mbarrier.arrive.expect_tx.shared.b64 _, [%0], %1;" :: "r"(a), "r"(b) : "memory")
#define MB_ARR_CL(addr, rk) \
    asm volatile("{\n\t.reg .b32 ra;\n\tmapa.shared::cluster.u32 ra, %0, %1;\n\t" \
                 "mbarrier.arrive.shared::cluster.b64 _, [ra];\n\t}" \
                 :: "r"(addr), "r"(rk) : "memory")
#define BULK_MC(dst, src, mbar) \
    asm volatile("cp.async.bulk.shared::cluster.global.mbarrier::complete_tx::bytes.multicast::cluster " \
                 "[%0], [%1], %2, [%3], %4;" \
                 :: "r"(dst), "l"(src), "r"(16384), "r"(mbar), "h"((unsigned short)0xF) : "memory")
#define MB_WAITP(mbar, ph) do { \
    asm volatile("{\n\t.reg .pred P1;\n\tWL_%=:\n\t" \
        "mbarrier.try_wait.parity.acquire.cta.shared::cta.b64 P1, [%0], %1, 0x989680;\n\t" \
        "@P1 bra.uni WD_%=;\n\tbra.uni WL_%=;\n\tWD_%=:\n\t}" \
        :: "r"(mbar), "r"(ph) : "memory"); \
} while (0)
#define CLUSTER_SYNC() do { \
    asm volatile("barrier.cluster.arrive.aligned;" ::: "memory"); \
    asm volatile("barrier.cluster.wait.aligned;" ::: "memory"); \
} while (0)

// ---------------- smem layout for k_mega (dynamic): 3-deep TMA ring ----------------
#define SM_WBUF   0          // 3 x 64KB weight tiles
#define SM_SQ     196608     // ull sq[256][4] = 8KB
#define SM_RED    204800     // ull red[3072] = 24KB (also expansion scratch)
#define SM_SL     229376     // float sL[16]
#define SM_REDJ   229440     // float redj[2][32]
#define SM_MBAR   229696     // 6 mbarriers (3 full + 3 empty)
#define SM_TOTAL  229760

// ---------------- K0: all weight prep in one launch ----------------
__global__ void k_prep(const float* __restrict__ wl, const float* __restrict__ wh) {
    int b = blockIdx.x;
    int tid = threadIdx.x;
    __shared__ float4 tile[32][33];
    int col = tid & 31, row8 = tid >> 5;
    if (b < 384) {
        int d = b >> 6, r = b & 63;
        int it = r >> 3, ot = r & 7;
        const float* base = wl + (size_t)d * 4 * QD * QD;
#pragma unroll
        for (int s = 0; s < 4; s++) {
            int oo = row8 + s * 8;
            int o = ot * 32 + oo, i = it * 32 + col;
            float wr = base[0 * QD * QD + o * QD + i];
            float wi = base[1 * QD * QD + o * QD + i];
            float wj = base[2 * QD * QD + o * QD + i];
            float wk = base[3 * QD * QD + o * QD + i];
            tile[oo][col] = make_float4(wr, wi, wj, wk);
        }
        __syncthreads();
#pragma unroll
        for (int s = 0; s < 4; s++) {
            int ii = row8 + s * 8;
            int i = it * 32 + ii, o = ot * 32 + col;
            g_wAll[((size_t)d * QD + i) * QD + o] = tile[col][ii];
        }
    } else if (b < 448) {
        int b2 = b - 384;
        int jt = b2 >> 3, kt = b2 & 7;
#pragma unroll
        for (int s = 0; s < 4; s++) {
            int jj = row8 + s * 8;
            int j = jt * 32 + jj, k4 = kt * 32 + col;
            tile[jj][col] = *(const float4*)(wh + (size_t)j * 1024 + k4 * 4);
        }
        __syncthreads();
#pragma unroll
        for (int s = 0; s < 4; s++) {
            int kk = row8 + s * 8;
            int k4 = kt * 32 + kk, j = jt * 32 + col;
            g_wAll[96 * 4096 + (size_t)k4 * 256 + j] = tile[col][kk];
        }
    } else {
        for (int k = tid; k < 1024; k += 256) g_wH256[k] = wh[(size_t)256 * 1024 + k];
    }
}

// ---------------- expansion stage (compile-time cq), 16 warps per token ----------------
template<int CQ>
__device__ __forceinline__ void exp_stage(const float* __restrict__ W,
                                          const float4* __restrict__ curb,
                                          float4* __restrict__ nxtb,
                                          int wh, int lane) {
    const int CQ2 = CQ * CQ;
    for (int o = wh; o < CQ; o += 16) {
        float dr = 0.f, di = 0.f, dj = 0.f, dk = 0.f;
        for (int i = lane; i < CQ; i += 32) {
            float4 q = curb[i];
            float wr = __ldg(W + o * CQ + i);
            float wi = __ldg(W + CQ2 + o * CQ + i);
            float wj = __ldg(W + 2 * CQ2 + o * CQ + i);
            float wk = __ldg(W + 3 * CQ2 + o * CQ + i);
            dr += wr * q.x - wi * q.y - wj * q.z - wk * q.w;
            di += wi * q.x + wr * q.y + wk * q.z - wj * q.w;
            dj += wj * q.x - wk * q.y + wr * q.z + wi * q.w;
            dk += wk * q.x + wj * q.y - wi * q.z + wr * q.w;
        }
#pragma unroll
        for (int off = 16; off; off >>= 1) {
            dr += __shfl_down_sync(0xFFFFFFFFu, dr, off);
            di += __shfl_down_sync(0xFFFFFFFFu, di, off);
            dj += __shfl_down_sync(0xFFFFFFFFu, dj, off);
            dk += __shfl_down_sync(0xFFFFFFFFu, dk, off);
        }
        if (lane == 0) {
            dr = tanhf(dr); di = tanhf(di); dj = tanhf(dj); dk = tanhf(dk);
            float4 q = curb[o];
            nxtb[o]      = make_float4(q.x + dr, q.y + di, q.z + dj, q.w + dk);
            nxtb[o + CQ] = make_float4(q.x - dr, q.y - di, q.z - dj, q.w - dk);
        }
    }
}

// ---------------- MEGA: expansion + 6 layers + stability + head (fused) ----------------
__global__ void __launch_bounds__(1024, 1) __cluster_dims__(4, 1, 1) k_mega(
    const float* __restrict__ emb,
    const float* __restrict__ e0, const float* __restrict__ e1,
    const float* __restrict__ e2, const float* __restrict__ e3,
    const float* __restrict__ e4, const float* __restrict__ e5,
    const float* __restrict__ e6, const float* __restrict__ e7) {
    extern __shared__ char sm[];
    uint32_t sb = smem_u32(sm);
    ull (*sq)[4]   = (ull(*)[4])(sm + SM_SQ);
    ull*  red      = (ull*)(sm + SM_RED);
    float* sL      = (float*)(sm + SM_SL);
    float (*redj)[32] = (float(*)[32])(sm + SM_REDJ);
    uint32_t mb = sb + SM_MBAR;   // full[i]=mb+8i, empty[i]=mb+24+8i

    int tid = threadIdx.x;
    int o = tid & 255, p = tid >> 8;
    uint32_t rank = ctarank();
    int b2 = blockIdx.x * 2;
    int t0 = b2 > 256 ? 256 : b2;
    int t1 = b2 + 1 > 256 ? 256 : b2 + 1;

    // mbarrier init, cluster sync, then TMA prefetch FIRST (overlaps expansion)
    if (tid == 0) {
#pragma unroll
        for (int i = 0; i < 3; i++) {
            MB_INIT(mb + i * 8, 1);
            MB_INIT(mb + 24 + i * 8, 4);
        }
    }
    __syncthreads();
    CLUSTER_SYNC();

    const char* wall = (const char*)g_wAll;
    if (tid == 0) {
#pragma unroll
        for (int nt = 0; nt < 3; nt++) {
            MB_EXPECT(mb + nt * 8, 65536);
            BULK_MC(sb + SM_WBUF + nt * 65536 + rank * 16384,
                    wall + (size_t)nt * 65536 + rank * 16384, mb + nt * 8);
        }
    }

    // ---------------- fused expansion: 2 tokens, 16 warps each, scratch = red ----------------
    {
        float4* exb = (float4*)red;              // 2 tokens x 2 buffers x 256 float4 = 16 KB
        int h = tid >> 9;                        // token half
        int wt = tid & 511;
        int wh = wt >> 5, lane = tid & 31;
        int mytok = h ? t1 : t0;
        float4* curb = exb + h * 512;
        float4* nxtb = curb + 256;
        if (wt == 0)
            curb[0] = make_float4(emb[mytok * 4 + 0], emb[mytok * 4 + 1],
                                  emb[mytok * 4 + 2], emb[mytok * 4 + 3]);
        __syncthreads();
        exp_stage<1>(e0, curb, nxtb, wh, lane);   __syncthreads();
        exp_stage<2>(e1, nxtb, curb, wh, lane);   __syncthreads();
        exp_stage<4>(e2, curb, nxtb, wh, lane);   __syncthreads();
        exp_stage<8>(e3, nxtb, curb, wh, lane);   __syncthreads();
        exp_stage<16>(e4, curb, nxtb, wh, lane);  __syncthreads();
        exp_stage<32>(e5, nxtb, curb, wh, lane);  __syncthreads();
        exp_stage<64>(e6, curb, nxtb, wh, lane);  __syncthreads();
        exp_stage<128>(e7, nxtb, curb, wh, lane); __syncthreads();
        // final q lives in exb + h*512 (buffer 0 of each token)
        if (tid < 512) {
            int half = tid >> 8;
            int oo = tid & 255;
            float4 a = exb[half * 512 + oo];
            ((float*)&sq[oo][0])[half] = a.x;
            ((float*)&sq[oo][1])[half] = a.y;
            ((float*)&sq[oo][2])[half] = a.z;
            ((float*)&sq[oo][3])[half] = a.w;
        }
    }
    __syncthreads();   // sq ready; red free for layer reductions

    int bufi = 0, ph = 0;   // ring position + parity (block-uniform)

    // ---------------- 6 quaternion layers (r10 proven) ----------------
    for (int d = 0; d < DEPTHN; d++) {
        ull P[16];
#pragma unroll
        for (int n = 0; n < 16; n++) P[n] = 0ull;

        for (int t = 0; t < 16; t++) {
            uint32_t fb = mb + bufi * 8, eb = mb + 24 + bufi * 8;
            MB_WAITP(fb, ph);
            const char* wtile = sm + SM_WBUF + bufi * 65536;
#pragma unroll
            for (int m = 0; m < 4; m++) {
                int il = p + 4 * m;
                float4 w = *(const float4*)(wtile + (((il << 8) + o) << 4));
                const ull* qp = &sq[t * 16 + il][0];
                ull wr = bcast2(w.x), wi = bcast2(w.y), wj = bcast2(w.z), wk = bcast2(w.w);
                ull2 qa = *(const ull2*)(qp);
                ull2 qc = *(const ull2*)(qp + 2);
                ull qr = qa.x, qi = qa.y, qj = qc.x, qk = qc.y;
                fma2(P[0],  wr, qr); fma2(P[1],  wr, qi); fma2(P[2],  wr, qj); fma2(P[3],  wr, qk);
                fma2(P[4],  wi, qr); fma2(P[5],  wi, qi); fma2(P[6],  wi, qj); fma2(P[7],  wi, qk);
                fma2(P[8],  wj, qr); fma2(P[9],  wj, qi); fma2(P[10], wj, qj); fma2(P[11], wj, qk);
                fma2(P[12], wk, qr); fma2(P[13], wk, qi); fma2(P[14], wk, qj); fma2(P[15], wk, qk);
            }
            __syncthreads();
            if (tid == 0) {
                MB_ARR_CL(eb, 0); MB_ARR_CL(eb, 1);
                MB_ARR_CL(eb, 2); MB_ARR_CL(eb, 3);
                int nt2 = d * 16 + t + 3;
                if (nt2 < 112) {
                    MB_WAITP(eb, ph);
                    MB_EXPECT(fb, 65536);
                    BULK_MC(sb + SM_WBUF + bufi * 65536 + rank * 16384,
                            wall + (size_t)nt2 * 65536 + rank * 16384, fb);
                }
            }
            bufi++; if (bufi == 3) { bufi = 0; ph ^= 1; }
        }

        // Hamilton combine + normalize (packed over token pair)
        ull dr = add2(add2(P[0],  P[5]  ^ NEG2), add2(P[10] ^ NEG2, P[15] ^ NEG2));
        ull di = add2(add2(P[4],  P[1]),         add2(P[14],        P[11] ^ NEG2));
        ull dj = add2(add2(P[8],  P[13] ^ NEG2), add2(P[2],         P[7]));
        ull dk = add2(add2(P[12], P[9]),         add2(P[6]  ^ NEG2, P[3]));

        if (p) {
            int idx = ((p - 1) * 256 + o) * 4;
            red[idx] = dr; red[idx + 1] = di; red[idx + 2] = dj; red[idx + 3] = dk;
        }
        __syncthreads();
        if (p == 0) {
#pragma unroll
            for (int s = 0; s < 3; s++) {
                int idx = (s * 256 + o) * 4;
                dr = add2(dr, red[idx]);
                di = add2(di, red[idx + 1]);
                dj = add2(dj, red[idx + 2]);
                dk = add2(dk, red[idx + 3]);
            }
            float2 R = unpack2(dr), I = unpack2(di), J = unpack2(dj), K = unpack2(dk);
            float n0 = sqrtf(R.x * R.x + I.x * I.x + J.x * J.x + K.x * K.x);
            float v0 = 1.0f / (n0 + 1e-8f);
            float n1 = sqrtf(R.y * R.y + I.y * I.y + J.y * J.y + K.y * K.y);
            float v1 = 1.0f / (n1 + 1e-8f);
            sq[o][0] = pack2f(R.x * v0, R.y * v1);
            sq[o][1] = pack2f(I.x * v0, I.y * v1);
            sq[o][2] = pack2f(J.x * v0, J.y * v1);
            sq[o][3] = pack2f(K.x * v0, K.y * v1);
        }
        __syncthreads();
    }

    // ---------------- stability: mean |q_r| per token ----------------
    if (p == 0) {
        float2 qr = unpack2(sq[o][0]);
        float a0 = fabsf(qr.x), a1 = fabsf(qr.y);
#pragma unroll
        for (int off = 16; off; off >>= 1) {
            a0 += __shfl_down_sync(0xFFFFFFFFu, a0, off);
            a1 += __shfl_down_sync(0xFFFFFFFFu, a1, off);
        }
        if ((o & 31) == 0) {
            sL[(o >> 5) * 2 + 0] = a0;
            sL[(o >> 5) * 2 + 1] = a1;
        }
    }

    // build head hq: red[0..511] token0 (h[2m],h[2m+1]) pairs, red[512..1023] token1
    {
        int half = tid >> 9, idx = tid & 511;
        int oo = idx >> 1;
        int c0 = (2 * idx) & 3;
        float2 v0 = unpack2(sq[oo][c0]);
        float2 v1 = unpack2(sq[oo][c0 + 1]);
        red[half * 512 + idx] = half ? pack2f(v0.y, v1.y) : pack2f(v0.x, v1.x);
    }
    __syncthreads();

    if (tid == 0) {
        float s0 = 0.f, s1 = 0.f;
#pragma unroll
        for (int w = 0; w < 8; w++) { s0 += sL[w * 2]; s1 += sL[w * 2 + 1]; }
        g_L[t0] = s0 * (1.0f / QD);
        g_L[t1] = s1 * (1.0f / QD);
    }

    // j == 256 column (k = tid over 1024)
    {
        float w256 = g_wH256[tid];
        float s0 = w256 * ((const float*)red)[tid];
        float s1 = w256 * ((const float*)red)[1024 + tid];
#pragma unroll
        for (int off = 16; off; off >>= 1) {
            s0 += __shfl_down_sync(0xFFFFFFFFu, s0, off);
            s1 += __shfl_down_sync(0xFFFFFFFFu, s1, off);
        }
        if ((tid & 31) == 0) {
            redj[0][tid >> 5] = s0;
            redj[1][tid >> 5] = s1;
        }
    }

    // ---------------- head GEMM (tiles 96..111 of the same stream) ----------------
    {
        int j = o;
        ull a0 = 0ull, a1 = 0ull;
        for (int t = 0; t < 16; t++) {
            uint32_t fb = mb + bufi * 8, eb = mb + 24 + bufi * 8;
            MB_WAITP(fb, ph);
            const char* wtile = sm + SM_WBUF + bufi * 65536;
#pragma unroll
            for (int m = 0; m < 4; m++) {
                int il = p + 4 * m;
                int k4 = t * 16 + il;
                float4 w = *(const float4*)(wtile + (((il << 8) + j) << 4));
                ull w01 = *(const ull*)&w.x;
                ull w23 = *(const ull*)&w.z;
                ull2 qa = *(const ull2*)(red + 2 * k4);          // token0
                ull2 qb = *(const ull2*)(red + 512 + 2 * k4);    // token1
                fma2(a0, w01, qa.x); fma2(a0, w23, qa.y);
                fma2(a1, w01, qb.x); fma2(a1, w23, qb.y);
            }
            __syncthreads();
            if (tid == 0) {
                MB_ARR_CL(eb, 0); MB_ARR_CL(eb, 1);
                MB_ARR_CL(eb, 2); MB_ARR_CL(eb, 3);
                int nt2 = 96 + t + 3;
                if (nt2 < 112) {
                    MB_WAITP(eb, ph);
                    MB_EXPECT(fb, 65536);
                    BULK_MC(sb + SM_WBUF + bufi * 65536 + rank * 16384,
                            wall + (size_t)nt2 * 65536 + rank * 16384, fb);
                }
            }
            bufi++; if (bufi == 3) { bufi = 0; ph ^= 1; }
        }

        ull* redh = red + 1024;   // token0: [0..767], token1: [768..1535]
        if (p) {
            redh[(p - 1) * 256 + j]       = a0;
            redh[768 + (p - 1) * 256 + j] = a1;
        }
        __syncthreads();
        if (p == 0) {
#pragma unroll
            for (int s = 0; s < 3; s++) {
                a0 = add2(a0, redh[s * 256 + j]);
                a1 = add2(a1, redh[768 + s * 256 + j]);
            }
            float2 r0 = unpack2(a0), r1 = unpack2(a1);
            g_logits[(size_t)t0 * VOCABN + j] = r0.x + r0.y;
            g_logits[(size_t)t1 * VOCABN + j] = r1.x + r1.y;
        }
        if (tid == 0) {
            float s0 = 0.f, s1 = 0.f;
#pragma unroll
            for (int w = 0; w < 32; w++) { s0 += redj[0][w]; s1 += redj[1][w]; }
            g_logits[(size_t)t0 * VOCABN + 256] = s0;
            g_logits[(size_t)t1 * VOCABN + 256] = s1;
        }
    }

    __syncthreads();
    CLUSTER_SYNC();   // no CTA exits while peer multicasts / remote arrives are in flight
}

// ---------------- K5: gather (r10 proven loop) + fused final loss ----------------
__global__ void k_gather(const int* __restrict__ x, float* __restrict__ out, int out_size) {
    __shared__ float ls[8];
    __shared__ float redf[256];
    __shared__ int is_last;
    int warp = threadIdx.x >> 5, lane = threadIdx.x & 31;
    int pp = blockIdx.x * 8 + warp;
    int tok = x[pp];
    const float* row = g_logits + (size_t)tok * VOCABN;
    float* orow = out + (size_t)pp * VOCABN;
    for (int v = lane; v < VOCABN; v += 32)
        orow[v] = row[v];
    if (lane == 0) ls[warp] = g_L[tok];
    __syncthreads();
    if (threadIdx.x == 0) {
        float s = 0.f;
#pragma unroll
        for (int w = 0; w < 8; w++) s += ls[w];
        g_part[blockIdx.x] = s;
        __threadfence();
        unsigned old = atomicAdd(&g_cnt, 1u);
        is_last = (old == (unsigned)(NPOS / 8 - 1));
    }
    __syncthreads();
    if (is_last) {
        __threadfence();
        int tid = threadIdx.x;
        float s = 0.f;
        for (int i = tid; i < NPOS / 8; i += 256)
            s += g_part[i];
        redf[tid] = s;
        __syncthreads();
        for (int k2 = 128; k2 > 0; k2 >>= 1) {
            if (tid < k2) redf[tid] += redf[tid + k2];
            __syncthreads();
        }
        if (tid == 0) {
            if (out_size > BSV) out[BSV] = redf[0] * (1.0f / NPOS);
            g_cnt = 0;   // reset for deterministic replay
        }
    }
}

// ---------------- launch ----------------
extern "C" void kernel_launch(void* const* d_in, const int* in_sizes, int n_in,
                              void* d_out, int out_size) {
    (void)in_sizes; (void)n_in;
    const int*   x   = (const int*)d_in[0];
    const float* emb = (const float*)d_in[1];
    const float* e0  = (const float*)d_in[2];
    const float* e1  = (const float*)d_in[3];
    const float* e2  = (const float*)d_in[4];
    const float* e3  = (const float*)d_in[5];
    const float* e4  = (const float*)d_in[6];
    const float* e5  = (const float*)d_in[7];
    const float* e6  = (const float*)d_in[8];
    const float* e7  = (const float*)d_in[9];
    const float* wl  = (const float*)d_in[10];
    const float* wh  = (const float*)d_in[11];
    float* out = (float*)d_out;

    static int smem_set = 0;
    if (!smem_set) {
        cudaFuncSetAttribute(k_mega, cudaFuncAttributeMaxDynamicSharedMemorySize, SM_TOTAL);
        smem_set = 1;
    }

    k_prep<<<449, 256>>>(wl, wh);
    k_mega<<<132, 1024, SM_TOTAL>>>(emb, e0, e1, e2, e3, e4, e5, e6, e7);
    k_gather<<<NPOS / 8, 256>>>(x, out, out_size);
}